// round 11
// baseline (speedup 1.0000x reference)
#include <cuda_runtime.h>
#include <cuda_bf16.h>
#include <cstdint>
#include <math.h>
#include <float.h>

#define NB 2
#define NN 4096
#define NC 128
#define NK 8
#define UVS 4100   // padded stride for u/v so each batch slice is 16B-aligned
#define KS 768     // 6-term split: A=[h|m|h|l|h|m], B=[h|h|m|h|l|m]
#define NBLK 512   // row-blocks per batch in fused sinkhorn pass (8 rows each)

#define NORMC  (-9.010913347279289f)   // -log(8192)
#define LOGMC  (-0.6931471805599453f)  // log(4096) - log(8192)

// -------- scratch (static device globals; no allocation) --------
__device__ __nv_bfloat16 g_Ah[(size_t)NB * NN * KS];
__device__ __nv_bfloat16 g_Bh[(size_t)NB * NN * KS];
__device__ float g_u[NB * UVS];
__device__ float g_v[NB * UVS];
__device__ float g_pcol[(size_t)NB * NBLK * NN];  // per-block column partials (16.8MB)
__device__ float g_esum[NB];                      // sum_r exp(u[r]) for dustbin col
__device__ float g_tkv[NB * NN * NK];
__device__ float g_tkp[NB * NN * NK * 2];
__device__ float g_geo[NB * NN * NK];

// -------- reduction helpers --------
__device__ __forceinline__ float warpSumF(float v) {
#pragma unroll
    for (int o = 16; o; o >>= 1) v += __shfl_xor_sync(0xffffffffu, v, o);
    return v;
}
__device__ __forceinline__ float blockReduceSum(float v, float* sw) {
    v = warpSumF(v);
    int wid = threadIdx.x >> 5, lane = threadIdx.x & 31;
    __syncthreads();
    if (lane == 0) sw[wid] = v;
    __syncthreads();
    if (wid == 0) {
        float x = (lane < 8) ? sw[lane] : 0.f;
        x = warpSumF(x);
        if (lane == 0) sw[0] = x;
    }
    __syncthreads();
    return sw[0];
}

// -------- mma helpers --------
__device__ __forceinline__ uint32_t smem_u32(const void* p) {
    return (uint32_t)__cvta_generic_to_shared(p);
}
__device__ __forceinline__ void ldsm_x4(uint32_t& r0, uint32_t& r1, uint32_t& r2,
                                        uint32_t& r3, uint32_t addr) {
    asm volatile("ldmatrix.sync.aligned.m8n8.x4.shared.b16 {%0,%1,%2,%3}, [%4];"
                 : "=r"(r0), "=r"(r1), "=r"(r2), "=r"(r3) : "r"(addr));
}
__device__ __forceinline__ void mma16816(float* d, const uint32_t* a, const uint32_t* b) {
    asm volatile(
        "mma.sync.aligned.m16n8k16.row.col.f32.bf16.bf16.f32 "
        "{%0,%1,%2,%3}, {%4,%5,%6,%7}, {%8,%9}, {%0,%1,%2,%3};"
        : "+f"(d[0]), "+f"(d[1]), "+f"(d[2]), "+f"(d[3])
        : "r"(a[0]), "r"(a[1]), "r"(a[2]), "r"(a[3]), "r"(b[0]), "r"(b[1]));
}

// -------- row L2 normalize + bf16 3-limb split --------
__global__ void __launch_bounds__(256) normalize_kernel(const float* __restrict__ fA,
                                                        const float* __restrict__ fB) {
    int gw = (blockIdx.x * blockDim.x + threadIdx.x) >> 5;
    int lane = threadIdx.x & 31;
    if (gw >= 2 * NB * NN) return;
    int row = gw & (NB * NN - 1);
    bool isA = gw < NB * NN;
    const float* src = isA ? fA : fB;
    const float* p = src + (size_t)row * NC;
    float x[4]; float ss = 0.f;
#pragma unroll
    for (int l = 0; l < 4; l++) { x[l] = p[lane + l * 32]; ss += x[l] * x[l]; }
    ss = warpSumF(ss);
    float sc = 1.f / fmaxf(sqrtf(ss), 1e-12f);
    __nv_bfloat16* q = (isA ? g_Ah : g_Bh) + (size_t)row * KS;
#pragma unroll
    for (int l = 0; l < 4; l++) {
        float v = x[l] * sc;
        __nv_bfloat16 h = __float2bfloat16(v);
        float r1 = v - __bfloat162float(h);
        __nv_bfloat16 m = __float2bfloat16(r1);
        float r2 = r1 - __bfloat162float(m);
        __nv_bfloat16 lo = __float2bfloat16(r2);
        int c = lane + l * 32;
        if (isA) {
            q[c]       = h;  q[c + 128] = m;  q[c + 256] = h;
            q[c + 384] = lo; q[c + 512] = h;  q[c + 640] = m;
        } else {
            q[c]       = h;  q[c + 128] = h;  q[c + 256] = m;
            q[c + 384] = h;  q[c + 512] = lo; q[c + 640] = m;
        }
    }
}

// -------- zero v --------
__global__ void zero_v_kernel() {
    int t = blockIdx.x * blockDim.x + threadIdx.x;
    if (t < NB * UVS) g_v[t] = 0.f;
}

// -------- bf16 tensor-core GEMM (K=768, synchronous, 2 CTA/SM) --------
__global__ void __launch_bounds__(256, 2) gemm_kernel(float* __restrict__ C) {
    __shared__ __align__(16) unsigned char sm[32 * 1024];   // A 16K + B 16K
    const int b = blockIdx.z;
    const __nv_bfloat16* Ag = g_Ah + (size_t)b * NN * KS;
    const __nv_bfloat16* Bg = g_Bh + (size_t)b * NN * KS;
    float* Cb = C + (size_t)b * NN * NN;

    int tid = threadIdx.x, lane = tid & 31, wid = tid >> 5;
    int m_w = (wid & 1) * 64, n_w = (wid >> 1) * 32;
    int m0 = blockIdx.x * 128, n0 = blockIdx.y * 128;
    uint32_t smA = smem_u32(sm), smB = smA + 16384;

    float acc[4][4][4];
#pragma unroll
    for (int i = 0; i < 4; i++)
#pragma unroll
        for (int j = 0; j < 4; j++)
#pragma unroll
            for (int e = 0; e < 4; e++) acc[i][j][e] = 0.f;

    for (int kc = 0; kc < 12; kc++) {
        // load 128x64 bf16 chunks of A and B, swizzled 128B rows
#pragma unroll
        for (int q = tid; q < 2048; q += 256) {
            int isB = q >= 1024;
            int qq = q & 1023;
            int row = qq >> 3, c16 = qq & 7;
            const __nv_bfloat16* srcp = isB ? Bg : Ag;
            int grow = (isB ? n0 : m0) + row;
            uint4 w = *(const uint4*)&srcp[(size_t)grow * KS + kc * 64 + c16 * 8];
            int sw = (c16 * 16) ^ ((row & 7) * 16);
            *(uint4*)(sm + isB * 16384 + row * 128 + sw) = w;
        }
        __syncthreads();
#pragma unroll
        for (int ks = 0; ks < 4; ks++) {
            int kb = ks * 16;
            uint32_t a[4][4], bfr[4][2];
#pragma unroll
            for (int mi = 0; mi < 4; mi++) {
                int row = m_w + mi * 16 + (lane & 15);
                int col = kb + ((lane >> 4) << 3);
                uint32_t addr = smA + row * 128 + ((col * 2) ^ ((row & 7) * 16));
                ldsm_x4(a[mi][0], a[mi][1], a[mi][2], a[mi][3], addr);
            }
#pragma unroll
            for (int g = 0; g < 2; g++) {
                int row = n_w + g * 16 + ((lane >> 4) << 3) + (lane & 7);
                int col = kb + ((lane >> 3) & 1) * 8;
                uint32_t addr = smB + row * 128 + ((col * 2) ^ ((row & 7) * 16));
                uint32_t r0, r1, r2, r3;
                ldsm_x4(r0, r1, r2, r3, addr);
                bfr[2 * g][0] = r0; bfr[2 * g][1] = r1;
                bfr[2 * g + 1][0] = r2; bfr[2 * g + 1][1] = r3;
            }
#pragma unroll
            for (int mi = 0; mi < 4; mi++)
#pragma unroll
                for (int ni = 0; ni < 4; ni++)
                    mma16816(acc[mi][ni], a[mi], bfr[ni]);
        }
        __syncthreads();
    }

    int r0l = lane >> 2, c0l = (lane & 3) * 2;
#pragma unroll
    for (int mi = 0; mi < 4; mi++)
#pragma unroll
        for (int hf = 0; hf < 2; hf++) {
            int r = m_w + mi * 16 + r0l + hf * 8;
            size_t ro = (size_t)(m0 + r) * NN + n0 + n_w;
#pragma unroll
            for (int ni = 0; ni < 4; ni++) {
                float2 v = make_float2(acc[mi][ni][hf * 2], acc[mi][ni][hf * 2 + 1]);
                *(float2*)&Cb[ro + ni * 8 + c0l] = v;
            }
        }
}

// -------- fused Sinkhorn pass: u-update (8 rows/block) + column partials --------
// u[r] = NORMC - 20 - log( sum_j exp(20 s + v_old[j] - 20) + exp(v_old[N]-20) )
// pcol[blk][j] = sum_{r in blk} exp(20 s + v_old[j] + u_new[r])   (v_old factor
//                divided back out in finalize_v)
__global__ void __launch_bounds__(256) sink_uv_kernel(const float* __restrict__ sim) {
    __shared__ float sw[32];
    int blk = blockIdx.x, b = blockIdx.y, tid = threadIdx.x;
    int r0 = blk * 8;
    const float* vv = g_v + b * UVS;
    const float4* vv4 = (const float4*)vv;
    float vreg[16];
#pragma unroll
    for (int k = 0; k < 4; k++) {
        float4 t = vv4[tid + (k << 8)];
        vreg[4 * k] = t.x; vreg[4 * k + 1] = t.y;
        vreg[4 * k + 2] = t.z; vreg[4 * k + 3] = t.w;
    }
    float vN = vv[NN];
    float acc[16];
#pragma unroll
    for (int k = 0; k < 16; k++) acc[k] = 0.f;

    for (int rr = 0; rr < 8; rr++) {
        int r = r0 + rr;
        const float4* s4 = (const float4*)(sim + (size_t)b * NN * NN + (size_t)r * NN);
        float e[16];
        float s = 0.f;
#pragma unroll
        for (int k = 0; k < 4; k++) {
            float4 sv = s4[tid + (k << 8)];
            e[4 * k]     = __expf(fmaf(20.f, sv.x, vreg[4 * k])     - 20.f);
            e[4 * k + 1] = __expf(fmaf(20.f, sv.y, vreg[4 * k + 1]) - 20.f);
            e[4 * k + 2] = __expf(fmaf(20.f, sv.z, vreg[4 * k + 2]) - 20.f);
            e[4 * k + 3] = __expf(fmaf(20.f, sv.w, vreg[4 * k + 3]) - 20.f);
            s += e[4 * k] + e[4 * k + 1] + e[4 * k + 2] + e[4 * k + 3];
        }
        if (tid == 0) s += __expf(vN - 20.f);
        float S = blockReduceSum(s, sw);
        float u_r = NORMC - 20.f - __logf(S);
        if (tid == 0) g_u[b * UVS + r] = u_r;
        float sc = __expf(u_r + 20.f);
#pragma unroll
        for (int k = 0; k < 16; k++) acc[k] = fmaf(e[k], sc, acc[k]);
    }
    // store partials matching the j layout: acc[4k+l] holds j = 4*(tid+256k)+l
    float4* pc4 = (float4*)(g_pcol + ((size_t)b * NBLK + blk) * NN);
#pragma unroll
    for (int k = 0; k < 4; k++)
        pc4[tid + (k << 8)] = make_float4(acc[4 * k], acc[4 * k + 1],
                                          acc[4 * k + 2], acc[4 * k + 3]);
}

// -------- dustbin-row u[N] (from v_old) + expsum over new u --------
__global__ void __launch_bounds__(256) uN_kernel() {
    __shared__ float sw[32];
    int b = blockIdx.x, tid = threadIdx.x;
    const float* vv = g_v + b * UVS;
    float s = 0.f;
    for (int j = tid; j <= NN; j += 256) s += __expf(vv[j]);
    float S = blockReduceSum(s, sw);
    float uN = LOGMC - __logf(S);
    if (tid == 0) g_u[b * UVS + NN] = uN;
    // expsum of new u over rows (for dustbin column update)
    const float* uu = g_u + b * UVS;
    float e = 0.f;
    for (int r = tid; r < NN; r += 256) e += __expf(uu[r]);
    float E = blockReduceSum(e, sw);
    if (tid == 0) g_esum[b] = E;
}

// -------- finalize v from column partials (divide out spurious exp(v_old[j])) ----
__global__ void __launch_bounds__(256) finalize_v_kernel() {
    int b = blockIdx.y;
    int j = blockIdx.x * 256 + threadIdx.x;
    if (j > NN) return;
    float uN = g_u[b * UVS + NN];
    float v;
    if (j < NN) {
        float v_old = g_v[b * UVS + j];
        const float* pc = g_pcol + (size_t)b * NBLK * NN + j;
        float s = 0.f;
#pragma unroll 8
        for (int blk = 0; blk < NBLK; blk++) s += pc[(size_t)blk * NN];
        // pcol carries exp(v_old[j]); true lse term is s * exp(-v_old[j])
        v = NORMC - __logf(fmaf(s, __expf(-v_old), __expf(uN)));
    } else {
        v = LOGMC - __logf(g_esum[b] + __expf(uN));
    }
    g_v[b * UVS + j] = v;
}

// -------- per-row: entropy + top-8 --------
__global__ void __launch_bounds__(256) row_final_kernel(const float* __restrict__ sim,
                                                        const float* __restrict__ posB,
                                                        float* __restrict__ ent_out) {
    __shared__ float a[NN];
    __shared__ float sw[32];
    __shared__ int   swi[32];
    __shared__ float s_bv;
    __shared__ int   s_bi;
    int r = blockIdx.x, b = blockIdx.y, tid = threadIdx.x;
    const float4* vv4 = (const float4*)(g_v + b * UVS);
    const float4* s4 = (const float4*)(sim + (size_t)b * NN * NN + (size_t)r * NN);
    float ui = g_u[b * UVS + r];
    float4 tv[4];
#pragma unroll
    for (int k = 0; k < 4; k++) {
        int idx = tid + (k << 8);
        float4 s = s4[idx], v = vv4[idx];
        tv[k].x = fmaf(20.f, s.x, v.x); tv[k].y = fmaf(20.f, s.y, v.y);
        tv[k].z = fmaf(20.f, s.z, v.z); tv[k].w = fmaf(20.f, s.w, v.w);
        ((float4*)a)[idx] = tv[k];
    }
    float s = 0.f, e = 0.f;
#pragma unroll
    for (int k = 0; k < 4; k++) {
        s += __expf(tv[k].x + ui) + __expf(tv[k].y + ui)
           + __expf(tv[k].z + ui) + __expf(tv[k].w + ui);
    }
    float S = blockReduceSum(s, sw);
    float inv = 1.f / (S + 1e-8f);
#pragma unroll
    for (int k = 0; k < 4; k++) {
        float p;
        p = __expf(tv[k].x + ui) * inv; e -= p * __logf(p + 1e-8f);
        p = __expf(tv[k].y + ui) * inv; e -= p * __logf(p + 1e-8f);
        p = __expf(tv[k].z + ui) * inv; e -= p * __logf(p + 1e-8f);
        p = __expf(tv[k].w + ui) * inv; e -= p * __logf(p + 1e-8f);
    }
    float E = blockReduceSum(e, sw);
    if (tid == 0) ent_out[b * NN + r] = E;
    __syncthreads();
    long base = ((long)(b * NN + r)) * NK;
    int wid = tid >> 5, lane = tid & 31;
    for (int t = 0; t < NK; t++) {
        float bv = -FLT_MAX; int bi = 0;
#pragma unroll
        for (int k = 0; k < 16; k++) {
            int j = tid + (k << 8);
            float x = a[j];
            if (x > bv) { bv = x; bi = j; }
        }
#pragma unroll
        for (int o = 16; o; o >>= 1) {
            float ov = __shfl_xor_sync(0xffffffffu, bv, o);
            int   oi = __shfl_xor_sync(0xffffffffu, bi, o);
            if (ov > bv || (ov == bv && oi < bi)) { bv = ov; bi = oi; }
        }
        __syncthreads();
        if (lane == 0) { sw[wid] = bv; swi[wid] = bi; }
        __syncthreads();
        if (wid == 0) {
            float x = (lane < 8) ? sw[lane] : -FLT_MAX;
            int  xi = (lane < 8) ? swi[lane] : 0;
#pragma unroll
            for (int o = 4; o; o >>= 1) {
                float ov = __shfl_xor_sync(0xffffffffu, x, o);
                int   oi = __shfl_xor_sync(0xffffffffu, xi, o);
                if (ov > x || (ov == x && oi < xi)) { x = ov; xi = oi; }
            }
            if (lane == 0) { s_bv = x; s_bi = xi; }
        }
        __syncthreads();
        if (tid == 0) {
            int idx = s_bi;
            g_tkv[base + t] = expf(s_bv + ui);
            float px = posB[((size_t)b * NN + idx) * 2];
            float py = posB[((size_t)b * NN + idx) * 2 + 1];
            g_tkp[(base + t) * 2]     = px;
            g_tkp[(base + t) * 2 + 1] = py;
            a[idx] = -FLT_MAX;
        }
        __syncthreads();
    }
}

// -------- 7x7 local displacement variance (split over 4 z-slices) --------
__global__ void __launch_bounds__(256) geo_kernel(const float* __restrict__ posA) {
    __shared__ float dx[NN];
    __shared__ float dy[NN];
    int k = blockIdx.x, b = blockIdx.y, z = blockIdx.z, tid = threadIdx.x;
    for (int n = tid; n < NN; n += 256) {
        size_t tp = ((size_t)(b * NN + n) * NK + k) * 2;
        size_t pp = ((size_t)b * NN + n) * 2;
        dx[n] = g_tkp[tp]     - posA[pp];
        dy[n] = g_tkp[tp + 1] - posA[pp + 1];
    }
    __syncthreads();
    for (int n = z * 1024 + tid; n < (z + 1) * 1024; n += 256) {
        int h = n >> 6, w = n & 63;
        float s = 0.f; int cnt = 0;
        for (int di = -3; di <= 3; di++) {
            int hh = h + di;
            if ((unsigned)hh >= 64u) continue;
            for (int dj = -3; dj <= 3; dj++) {
                int ww = w + dj;
                if ((unsigned)ww >= 64u) continue;
                int m = hh * 64 + ww;
                s += dx[m] + dy[m];
                cnt += 2;
            }
        }
        float mean = s * (1.f / 98.f);
        float ssd = (float)(98 - cnt) * mean * mean;
        for (int di = -3; di <= 3; di++) {
            int hh = h + di;
            if ((unsigned)hh >= 64u) continue;
            for (int dj = -3; dj <= 3; dj++) {
                int ww = w + dj;
                if ((unsigned)ww >= 64u) continue;
                int m = hh * 64 + ww;
                float ax = dx[m] - mean, ay = dy[m] - mean;
                ssd += ax * ax + ay * ay;
            }
        }
        float var = ssd * (1.f / 97.f);
        g_geo[(size_t)(b * NN + n) * NK + k] = 1.f / (1.f + 100.f * var);
    }
}

// -------- softmax-combine -> refined warp --------
__global__ void combine_kernel(float* __restrict__ outRW) {
    int t = blockIdx.x * blockDim.x + threadIdx.x;
    if (t >= NB * NN) return;
    size_t base = (size_t)t * NK;
    float c[NK]; float m = -FLT_MAX;
#pragma unroll
    for (int k = 0; k < NK; k++) {
        c[k] = g_tkv[base + k] + 1.5f * g_geo[base + k];
        m = fmaxf(m, c[k]);
    }
    float sw = 0.f, rx = 0.f, ry = 0.f;
#pragma unroll
    for (int k = 0; k < NK; k++) {
        float w = expf((c[k] - m) * 20.f);
        sw += w;
        rx += g_tkp[(base + k) * 2]     * w;
        ry += g_tkp[(base + k) * 2 + 1] * w;
    }
    outRW[(size_t)t * 2]     = rx / sw;
    outRW[(size_t)t * 2 + 1] = ry / sw;
}

extern "C" void kernel_launch(void* const* d_in, const int* in_sizes, int n_in,
                              void* d_out, int out_size) {
    const float* fA = (const float*)d_in[0];
    const float* fB = (const float*)d_in[1];
    const float* pA = (const float*)d_in[2];
    const float* pB = (const float*)d_in[3];
    (void)in_sizes; (void)n_in; (void)out_size;

    float* out = (float*)d_out;
    float* out_rw  = out;                          // [2,4096,2]
    float* out_ent = out + NB * NN * 2;            // [2,4096]
    float* out_sim = out + NB * NN * 2 + NB * NN;  // [2,4096,4096]

    normalize_kernel<<<(2 * NB * NN * 32 + 255) / 256, 256>>>(fA, fB);
    zero_v_kernel<<<(NB * UVS + 255) / 256, 256>>>();
    gemm_kernel<<<dim3(32, 32, NB), 256>>>(out_sim);
    for (int it = 0; it < 5; it++) {
        sink_uv_kernel<<<dim3(NBLK, NB), 256>>>(out_sim);
        uN_kernel<<<NB, 256>>>();
        finalize_v_kernel<<<dim3((NN + 256) / 256 + 1, NB), 256>>>();
    }
    row_final_kernel<<<dim3(NN, NB), 256>>>(out_sim, pB, out_ent);
    geo_kernel<<<dim3(NK, NB, 4), 256>>>(pA);
    combine_kernel<<<(NB * NN + 255) / 256, 256>>>(out_rw);
}

// round 12
// speedup vs baseline: 1.1645x; 1.1645x over previous
#include <cuda_runtime.h>
#include <cuda_bf16.h>
#include <cstdint>
#include <math.h>
#include <float.h>

#define NB 2
#define NN 4096
#define NC 128
#define NK 8
#define UVS 4100   // padded stride for u/v so each batch slice is 16B-aligned
#define KS 768     // 6-term split: A=[h|m|h|l|h|m], B=[h|h|m|h|l|m]

#define NORMC  (-9.010913347279289f)   // -log(8192)
#define LOGMC  (-0.6931471805599453f)  // log(4096) - log(8192)

// -------- scratch (static device globals; no allocation) --------
__device__ __nv_bfloat16 g_Ah[(size_t)NB * NN * KS];
__device__ __nv_bfloat16 g_Bh[(size_t)NB * NN * KS];
__device__ float g_ST[(size_t)NB * NN * NN];   // 20 * sim^T  (134 MB)
__device__ float g_u[NB * UVS];
__device__ float g_v[NB * UVS];
__device__ float g_part[(size_t)NB * NN * 32];
__device__ float g_tkv[NB * NN * NK];
__device__ float g_tkp[NB * NN * NK * 2];
__device__ float g_geo[NB * NN * NK];

// -------- reduction helpers --------
__device__ __forceinline__ float warpSumF(float v) {
#pragma unroll
    for (int o = 16; o; o >>= 1) v += __shfl_xor_sync(0xffffffffu, v, o);
    return v;
}
__device__ __forceinline__ float blockReduceSum(float v, float* sw) {
    v = warpSumF(v);
    int wid = threadIdx.x >> 5, lane = threadIdx.x & 31;
    __syncthreads();
    if (lane == 0) sw[wid] = v;
    __syncthreads();
    if (wid == 0) {
        float x = (lane < 8) ? sw[lane] : 0.f;
        x = warpSumF(x);
        if (lane == 0) sw[0] = x;
    }
    __syncthreads();
    return sw[0];
}

// -------- mma helpers --------
__device__ __forceinline__ uint32_t smem_u32(const void* p) {
    return (uint32_t)__cvta_generic_to_shared(p);
}
__device__ __forceinline__ void ldsm_x4(uint32_t& r0, uint32_t& r1, uint32_t& r2,
                                        uint32_t& r3, uint32_t addr) {
    asm volatile("ldmatrix.sync.aligned.m8n8.x4.shared.b16 {%0,%1,%2,%3}, [%4];"
                 : "=r"(r0), "=r"(r1), "=r"(r2), "=r"(r3) : "r"(addr));
}
__device__ __forceinline__ void mma16816(float* d, const uint32_t* a, const uint32_t* b) {
    asm volatile(
        "mma.sync.aligned.m16n8k16.row.col.f32.bf16.bf16.f32 "
        "{%0,%1,%2,%3}, {%4,%5,%6,%7}, {%8,%9}, {%0,%1,%2,%3};"
        : "+f"(d[0]), "+f"(d[1]), "+f"(d[2]), "+f"(d[3])
        : "r"(a[0]), "r"(a[1]), "r"(a[2]), "r"(a[3]), "r"(b[0]), "r"(b[1]));
}

// -------- row L2 normalize + bf16 3-limb split --------
__global__ void __launch_bounds__(256) normalize_kernel(const float* __restrict__ fA,
                                                        const float* __restrict__ fB) {
    int gw = (blockIdx.x * blockDim.x + threadIdx.x) >> 5;
    int lane = threadIdx.x & 31;
    if (gw >= 2 * NB * NN) return;
    int row = gw & (NB * NN - 1);
    bool isA = gw < NB * NN;
    const float* src = isA ? fA : fB;
    const float* p = src + (size_t)row * NC;
    float x[4]; float ss = 0.f;
#pragma unroll
    for (int l = 0; l < 4; l++) { x[l] = p[lane + l * 32]; ss += x[l] * x[l]; }
    ss = warpSumF(ss);
    float sc = 1.f / fmaxf(sqrtf(ss), 1e-12f);
    __nv_bfloat16* q = (isA ? g_Ah : g_Bh) + (size_t)row * KS;
#pragma unroll
    for (int l = 0; l < 4; l++) {
        float v = x[l] * sc;
        __nv_bfloat16 h = __float2bfloat16(v);
        float r1 = v - __bfloat162float(h);
        __nv_bfloat16 m = __float2bfloat16(r1);
        float r2 = r1 - __bfloat162float(m);
        __nv_bfloat16 lo = __float2bfloat16(r2);
        int c = lane + l * 32;
        if (isA) {
            q[c]       = h;  q[c + 128] = m;  q[c + 256] = h;
            q[c + 384] = lo; q[c + 512] = h;  q[c + 640] = m;
        } else {
            q[c]       = h;  q[c + 128] = h;  q[c + 256] = m;
            q[c + 384] = h;  q[c + 512] = lo; q[c + 640] = m;
        }
    }
}

// -------- bf16 tensor-core GEMM (K=768, 6-term) + fused transpose + first-u --------
__global__ void __launch_bounds__(256, 2) gemm_kernel(float* __restrict__ C) {
    __shared__ __align__(16) unsigned char sm[33 * 1024];
    float* stg = (float*)sm;                   // [32][132] transpose staging
    float* pw  = (float*)(sm + 24576);         // [128][4] partial expsums

    const int b = blockIdx.z;
    const __nv_bfloat16* Ag = g_Ah + (size_t)b * NN * KS;
    const __nv_bfloat16* Bg = g_Bh + (size_t)b * NN * KS;
    float* Cb = C + (size_t)b * NN * NN;
    float* STb = g_ST + (size_t)b * NN * NN;

    int tid = threadIdx.x, lane = tid & 31, wid = tid >> 5;
    int m_w = (wid & 1) * 64, n_w = (wid >> 1) * 32;
    int m0 = blockIdx.x * 128, n0 = blockIdx.y * 128;
    uint32_t smA = smem_u32(sm), smB = smA + 16384;

    float acc[4][4][4];
#pragma unroll
    for (int i = 0; i < 4; i++)
#pragma unroll
        for (int j = 0; j < 4; j++)
#pragma unroll
            for (int e = 0; e < 4; e++) acc[i][j][e] = 0.f;

    for (int kc = 0; kc < 12; kc++) {
#pragma unroll
        for (int q = tid; q < 2048; q += 256) {
            int isB = q >= 1024;
            int qq = q & 1023;
            int row = qq >> 3, c16 = qq & 7;
            const __nv_bfloat16* srcp = isB ? Bg : Ag;
            int grow = (isB ? n0 : m0) + row;
            uint4 w = *(const uint4*)&srcp[(size_t)grow * KS + kc * 64 + c16 * 8];
            int sw = (c16 * 16) ^ ((row & 7) * 16);
            *(uint4*)(sm + isB * 16384 + row * 128 + sw) = w;
        }
        __syncthreads();
#pragma unroll
        for (int ks = 0; ks < 4; ks++) {
            int kb = ks * 16;
            uint32_t a[4][4], bfr[4][2];
#pragma unroll
            for (int mi = 0; mi < 4; mi++) {
                int row = m_w + mi * 16 + (lane & 15);
                int col = kb + ((lane >> 4) << 3);
                uint32_t addr = smA + row * 128 + ((col * 2) ^ ((row & 7) * 16));
                ldsm_x4(a[mi][0], a[mi][1], a[mi][2], a[mi][3], addr);
            }
#pragma unroll
            for (int g = 0; g < 2; g++) {
                int row = n_w + g * 16 + ((lane >> 4) << 3) + (lane & 7);
                int col = kb + ((lane >> 3) & 1) * 8;
                uint32_t addr = smB + row * 128 + ((col * 2) ^ ((row & 7) * 16));
                uint32_t r0, r1, r2, r3;
                ldsm_x4(r0, r1, r2, r3, addr);
                bfr[2 * g][0] = r0; bfr[2 * g][1] = r1;
                bfr[2 * g + 1][0] = r2; bfr[2 * g + 1][1] = r3;
            }
#pragma unroll
            for (int mi = 0; mi < 4; mi++)
#pragma unroll
                for (int ni = 0; ni < 4; ni++)
                    mma16816(acc[mi][ni], a[mi], bfr[ni]);
        }
        __syncthreads();
    }

    int r0l = lane >> 2, c0l = (lane & 3) * 2;
    // ---- sim store ----
#pragma unroll
    for (int mi = 0; mi < 4; mi++)
#pragma unroll
        for (int hf = 0; hf < 2; hf++) {
            int r = m_w + mi * 16 + r0l + hf * 8;
            size_t ro = (size_t)(m0 + r) * NN + n0 + n_w;
#pragma unroll
            for (int ni = 0; ni < 4; ni++) {
                float2 v = make_float2(acc[mi][ni][hf * 2], acc[mi][ni][hf * 2 + 1]);
                *(float2*)&Cb[ro + ni * 8 + c0l] = v;
            }
        }
    // ---- first-u partials ----
#pragma unroll
    for (int mi = 0; mi < 4; mi++)
#pragma unroll
        for (int hf = 0; hf < 2; hf++) {
            float s = 0.f;
#pragma unroll
            for (int ni = 0; ni < 4; ni++) {
                s += __expf(fmaf(20.f, acc[mi][ni][hf * 2], -20.f));
                s += __expf(fmaf(20.f, acc[mi][ni][hf * 2 + 1], -20.f));
            }
            s += __shfl_xor_sync(0xffffffffu, s, 1);
            s += __shfl_xor_sync(0xffffffffu, s, 2);
            if ((lane & 3) == 0)
                pw[(m_w + mi * 16 + r0l + hf * 8) * 4 + (wid >> 1)] = s;
        }
    __syncthreads();
    if (tid < 128) {
        float s = pw[tid * 4] + pw[tid * 4 + 1] + pw[tid * 4 + 2] + pw[tid * 4 + 3];
        g_part[((size_t)(b * NN + m0 + tid)) * 32 + blockIdx.y] = s;
    }
    // ---- 20*sim^T via smem staging (coalesced 512B rows) ----
    for (int ch = 0; ch < 4; ch++) {
        __syncthreads();
        if ((wid >> 1) == ch) {
#pragma unroll
            for (int mi = 0; mi < 4; mi++)
#pragma unroll
                for (int ni = 0; ni < 4; ni++) {
                    int nl = ni * 8 + c0l;
                    int m = m_w + mi * 16 + r0l;
                    stg[nl * 132 + m]           = 20.f * acc[mi][ni][0];
                    stg[(nl + 1) * 132 + m]     = 20.f * acc[mi][ni][1];
                    stg[nl * 132 + m + 8]       = 20.f * acc[mi][ni][2];
                    stg[(nl + 1) * 132 + m + 8] = 20.f * acc[mi][ni][3];
                }
        }
        __syncthreads();
#pragma unroll
        for (int q = tid; q < 1024; q += 256) {
            int rowq = q >> 5, c4 = (q & 31) * 4;
            float4 w = *(float4*)&stg[rowq * 132 + c4];
            *(float4*)&STb[(size_t)(n0 + ch * 32 + rowq) * NN + m0 + c4] = w;
        }
    }
}

// -------- finalize fused first u-update --------
__global__ void finalize_u_kernel() {
    int t = blockIdx.x * blockDim.x + threadIdx.x;
    if (t >= NB * (NN + 1)) return;
    int b = t / (NN + 1), r = t % (NN + 1);
    float u;
    if (r < NN) {
        const float* p = g_part + ((size_t)(b * NN + r)) * 32;
        float s = __expf(-20.f);
#pragma unroll
        for (int k = 0; k < 32; k++) s += p[k];
        u = NORMC - (20.f + __logf(s));
    } else {
        u = LOGMC - __logf((float)(NN + 1));
    }
    g_u[b * UVS + r] = u;
}

// -------- Sinkhorn u-update (no-shift direct expsum; args in [-30,+11]) --------
__global__ void __launch_bounds__(256) sink_u_kernel(const float* __restrict__ sim) {
    __shared__ float sw[32];
    int r = blockIdx.x, b = blockIdx.y, tid = threadIdx.x;
    const float* vv = g_v + b * UVS;
    const float4* vv4 = (const float4*)vv;
    float s = 0.f;
    if (r < NN) {
        const float4* s4 = (const float4*)(sim + (size_t)b * NN * NN + (size_t)r * NN);
#pragma unroll
        for (int k = 0; k < 4; k++) {
            int idx = tid + (k << 8);
            float4 sv = s4[idx], v = vv4[idx];
            s += __expf(fmaf(20.f, sv.x, v.x)) + __expf(fmaf(20.f, sv.y, v.y))
               + __expf(fmaf(20.f, sv.z, v.z)) + __expf(fmaf(20.f, sv.w, v.w));
        }
    } else {
#pragma unroll
        for (int k = 0; k < 4; k++) {
            float4 v = vv4[tid + (k << 8)];
            s += __expf(v.x) + __expf(v.y) + __expf(v.z) + __expf(v.w);
        }
    }
    if (tid == 0) s += __expf(vv[NN]);
    float S = blockReduceSum(s, sw);
    if (tid == 0)
        g_u[b * UVS + r] = ((r < NN) ? NORMC : LOGMC) - __logf(S);
}

// -------- Sinkhorn v-update (no-shift; ST holds 20*sim^T, args <= ~0) --------
__global__ void __launch_bounds__(256) sink_v_kernel() {
    __shared__ float sw[32];
    int r = blockIdx.x, b = blockIdx.y, tid = threadIdx.x;
    const float* uu = g_u + b * UVS;
    const float4* uu4 = (const float4*)uu;
    float s = 0.f;
    if (r < NN) {
        const float4* s4 = (const float4*)(g_ST + (size_t)b * NN * NN + (size_t)r * NN);
#pragma unroll
        for (int k = 0; k < 4; k++) {
            int idx = tid + (k << 8);
            float4 sv = s4[idx], u = uu4[idx];
            s += __expf(sv.x + u.x) + __expf(sv.y + u.y)
               + __expf(sv.z + u.z) + __expf(sv.w + u.w);
        }
    } else {
#pragma unroll
        for (int k = 0; k < 4; k++) {
            float4 u = uu4[tid + (k << 8)];
            s += __expf(u.x) + __expf(u.y) + __expf(u.z) + __expf(u.w);
        }
    }
    if (tid == 0) s += __expf(uu[NN]);
    float S = blockReduceSum(s, sw);
    if (tid == 0)
        g_v[b * UVS + r] = ((r < NN) ? NORMC : LOGMC) - __logf(S);
}

// -------- per-row: entropy + top-8 --------
__global__ void __launch_bounds__(256) row_final_kernel(const float* __restrict__ sim,
                                                        const float* __restrict__ posB,
                                                        float* __restrict__ ent_out) {
    __shared__ float a[NN];
    __shared__ float sw[32];
    __shared__ int   swi[32];
    __shared__ float s_bv;
    __shared__ int   s_bi;
    int r = blockIdx.x, b = blockIdx.y, tid = threadIdx.x;
    const float4* vv4 = (const float4*)(g_v + b * UVS);
    const float4* s4 = (const float4*)(sim + (size_t)b * NN * NN + (size_t)r * NN);
    float ui = g_u[b * UVS + r];
    float4 tv[4];
#pragma unroll
    for (int k = 0; k < 4; k++) {
        int idx = tid + (k << 8);
        float4 s = s4[idx], v = vv4[idx];
        tv[k].x = fmaf(20.f, s.x, v.x); tv[k].y = fmaf(20.f, s.y, v.y);
        tv[k].z = fmaf(20.f, s.z, v.z); tv[k].w = fmaf(20.f, s.w, v.w);
        ((float4*)a)[idx] = tv[k];
    }
    float s = 0.f, e = 0.f;
#pragma unroll
    for (int k = 0; k < 4; k++) {
        s += __expf(tv[k].x + ui) + __expf(tv[k].y + ui)
           + __expf(tv[k].z + ui) + __expf(tv[k].w + ui);
    }
    float S = blockReduceSum(s, sw);
    float inv = 1.f / (S + 1e-8f);
#pragma unroll
    for (int k = 0; k < 4; k++) {
        float p;
        p = __expf(tv[k].x + ui) * inv; e -= p * __logf(p + 1e-8f);
        p = __expf(tv[k].y + ui) * inv; e -= p * __logf(p + 1e-8f);
        p = __expf(tv[k].z + ui) * inv; e -= p * __logf(p + 1e-8f);
        p = __expf(tv[k].w + ui) * inv; e -= p * __logf(p + 1e-8f);
    }
    float E = blockReduceSum(e, sw);
    if (tid == 0) ent_out[b * NN + r] = E;
    __syncthreads();
    long base = ((long)(b * NN + r)) * NK;
    int wid = tid >> 5, lane = tid & 31;
    for (int t = 0; t < NK; t++) {
        float bv = -FLT_MAX; int bi = 0;
#pragma unroll
        for (int k = 0; k < 16; k++) {
            int j = tid + (k << 8);
            float x = a[j];
            if (x > bv) { bv = x; bi = j; }
        }
#pragma unroll
        for (int o = 16; o; o >>= 1) {
            float ov = __shfl_xor_sync(0xffffffffu, bv, o);
            int   oi = __shfl_xor_sync(0xffffffffu, bi, o);
            if (ov > bv || (ov == bv && oi < bi)) { bv = ov; bi = oi; }
        }
        __syncthreads();
        if (lane == 0) { sw[wid] = bv; swi[wid] = bi; }
        __syncthreads();
        if (wid == 0) {
            float x = (lane < 8) ? sw[lane] : -FLT_MAX;
            int  xi = (lane < 8) ? swi[lane] : 0;
#pragma unroll
            for (int o = 4; o; o >>= 1) {
                float ov = __shfl_xor_sync(0xffffffffu, x, o);
                int   oi = __shfl_xor_sync(0xffffffffu, xi, o);
                if (ov > x || (ov == x && oi < xi)) { x = ov; xi = oi; }
            }
            if (lane == 0) { s_bv = x; s_bi = xi; }
        }
        __syncthreads();
        if (tid == 0) {
            int idx = s_bi;
            g_tkv[base + t] = expf(s_bv + ui);
            float px = posB[((size_t)b * NN + idx) * 2];
            float py = posB[((size_t)b * NN + idx) * 2 + 1];
            g_tkp[(base + t) * 2]     = px;
            g_tkp[(base + t) * 2 + 1] = py;
            a[idx] = -FLT_MAX;
        }
        __syncthreads();
    }
}

// -------- 7x7 local displacement variance (split over 4 z-slices) --------
__global__ void __launch_bounds__(256) geo_kernel(const float* __restrict__ posA) {
    __shared__ float dx[NN];
    __shared__ float dy[NN];
    int k = blockIdx.x, b = blockIdx.y, z = blockIdx.z, tid = threadIdx.x;
    for (int n = tid; n < NN; n += 256) {
        size_t tp = ((size_t)(b * NN + n) * NK + k) * 2;
        size_t pp = ((size_t)b * NN + n) * 2;
        dx[n] = g_tkp[tp]     - posA[pp];
        dy[n] = g_tkp[tp + 1] - posA[pp + 1];
    }
    __syncthreads();
    for (int n = z * 1024 + tid; n < (z + 1) * 1024; n += 256) {
        int h = n >> 6, w = n & 63;
        float s = 0.f; int cnt = 0;
        for (int di = -3; di <= 3; di++) {
            int hh = h + di;
            if ((unsigned)hh >= 64u) continue;
            for (int dj = -3; dj <= 3; dj++) {
                int ww = w + dj;
                if ((unsigned)ww >= 64u) continue;
                int m = hh * 64 + ww;
                s += dx[m] + dy[m];
                cnt += 2;
            }
        }
        float mean = s * (1.f / 98.f);
        float ssd = (float)(98 - cnt) * mean * mean;
        for (int di = -3; di <= 3; di++) {
            int hh = h + di;
            if ((unsigned)hh >= 64u) continue;
            for (int dj = -3; dj <= 3; dj++) {
                int ww = w + dj;
                if ((unsigned)ww >= 64u) continue;
                int m = hh * 64 + ww;
                float ax = dx[m] - mean, ay = dy[m] - mean;
                ssd += ax * ax + ay * ay;
            }
        }
        float var = ssd * (1.f / 97.f);
        g_geo[(size_t)(b * NN + n) * NK + k] = 1.f / (1.f + 100.f * var);
    }
}

// -------- softmax-combine -> refined warp --------
__global__ void combine_kernel(float* __restrict__ outRW) {
    int t = blockIdx.x * blockDim.x + threadIdx.x;
    if (t >= NB * NN) return;
    size_t base = (size_t)t * NK;
    float c[NK]; float m = -FLT_MAX;
#pragma unroll
    for (int k = 0; k < NK; k++) {
        c[k] = g_tkv[base + k] + 1.5f * g_geo[base + k];
        m = fmaxf(m, c[k]);
    }
    float sw = 0.f, rx = 0.f, ry = 0.f;
#pragma unroll
    for (int k = 0; k < NK; k++) {
        float w = expf((c[k] - m) * 20.f);
        sw += w;
        rx += g_tkp[(base + k) * 2]     * w;
        ry += g_tkp[(base + k) * 2 + 1] * w;
    }
    outRW[(size_t)t * 2]     = rx / sw;
    outRW[(size_t)t * 2 + 1] = ry / sw;
}

extern "C" void kernel_launch(void* const* d_in, const int* in_sizes, int n_in,
                              void* d_out, int out_size) {
    const float* fA = (const float*)d_in[0];
    const float* fB = (const float*)d_in[1];
    const float* pA = (const float*)d_in[2];
    const float* pB = (const float*)d_in[3];
    (void)in_sizes; (void)n_in; (void)out_size;

    float* out = (float*)d_out;
    float* out_rw  = out;                          // [2,4096,2]
    float* out_ent = out + NB * NN * 2;            // [2,4096]
    float* out_sim = out + NB * NN * 2 + NB * NN;  // [2,4096,4096]

    normalize_kernel<<<(2 * NB * NN * 32 + 255) / 256, 256>>>(fA, fB);
    gemm_kernel<<<dim3(32, 32, NB), 256>>>(out_sim);
    finalize_u_kernel<<<(NB * (NN + 1) + 255) / 256, 256>>>();
    sink_v_kernel<<<dim3(NN + 1, NB), 256>>>();
    for (int it = 0; it < 4; it++) {
        sink_u_kernel<<<dim3(NN + 1, NB), 256>>>(out_sim);
        sink_v_kernel<<<dim3(NN + 1, NB), 256>>>();
    }
    row_final_kernel<<<dim3(NN, NB), 256>>>(out_sim, pB, out_ent);
    geo_kernel<<<dim3(NK, NB, 4), 256>>>(pA);
    combine_kernel<<<(NB * NN + 255) / 256, 256>>>(out_rw);
}

// round 13
// speedup vs baseline: 1.2431x; 1.0675x over previous
#include <cuda_runtime.h>
#include <cuda_bf16.h>
#include <cstdint>
#include <math.h>
#include <float.h>

#define NB 2
#define NN 4096
#define NC 128
#define NK 8
#define UVS 4100   // padded stride for u/v so each batch slice is 16B-aligned
#define KS 768     // 6-term split: A=[h|m|h|l|h|m], B=[h|h|m|h|l|m]
#define NBLK 256   // row-blocks per batch in fused sinkhorn pass (16 rows each)
#define NFB 17     // finalize blocks per batch (17*256 >= 4097)

#define NORMC  (-9.010913347279289f)   // -log(8192)
#define LOGMC  (-0.6931471805599453f)  // log(4096) - log(8192)

// -------- scratch (static device globals; no allocation) --------
__device__ __nv_bfloat16 g_Ah[(size_t)NB * NN * KS];
__device__ __nv_bfloat16 g_Bh[(size_t)NB * NN * KS];
__device__ float g_u[NB * UVS];
__device__ float g_v[NB * UVS];
__device__ float g_pcol[(size_t)NB * NBLK * NN];  // column partials (8.4MB)
__device__ float g_upart[NB * NBLK];              // per-block sum exp(u_new)
__device__ float g_vpart[NB * 2 * NFB];           // ping-pong per-block sum exp(v_new)
__device__ float g_tkv[NB * NN * NK];
__device__ float g_tkp[NB * NN * NK * 2];
__device__ float g_geo[NB * NN * NK];

// -------- reduction helpers --------
__device__ __forceinline__ float warpSumF(float v) {
#pragma unroll
    for (int o = 16; o; o >>= 1) v += __shfl_xor_sync(0xffffffffu, v, o);
    return v;
}
__device__ __forceinline__ float blockReduceSum(float v, float* sw) {
    v = warpSumF(v);
    int wid = threadIdx.x >> 5, lane = threadIdx.x & 31;
    __syncthreads();
    if (lane == 0) sw[wid] = v;
    __syncthreads();
    if (wid == 0) {
        float x = (lane < 8) ? sw[lane] : 0.f;
        x = warpSumF(x);
        if (lane == 0) sw[0] = x;
    }
    __syncthreads();
    return sw[0];
}

// -------- mma helpers --------
__device__ __forceinline__ uint32_t smem_u32(const void* p) {
    return (uint32_t)__cvta_generic_to_shared(p);
}
__device__ __forceinline__ void ldsm_x4(uint32_t& r0, uint32_t& r1, uint32_t& r2,
                                        uint32_t& r3, uint32_t addr) {
    asm volatile("ldmatrix.sync.aligned.m8n8.x4.shared.b16 {%0,%1,%2,%3}, [%4];"
                 : "=r"(r0), "=r"(r1), "=r"(r2), "=r"(r3) : "r"(addr));
}
__device__ __forceinline__ void mma16816(float* d, const uint32_t* a, const uint32_t* b) {
    asm volatile(
        "mma.sync.aligned.m16n8k16.row.col.f32.bf16.bf16.f32 "
        "{%0,%1,%2,%3}, {%4,%5,%6,%7}, {%8,%9}, {%0,%1,%2,%3};"
        : "+f"(d[0]), "+f"(d[1]), "+f"(d[2]), "+f"(d[3])
        : "r"(a[0]), "r"(a[1]), "r"(a[2]), "r"(a[3]), "r"(b[0]), "r"(b[1]));
}

// -------- row L2 normalize + bf16 3-limb split --------
__global__ void __launch_bounds__(256) normalize_kernel(const float* __restrict__ fA,
                                                        const float* __restrict__ fB) {
    int gw = (blockIdx.x * blockDim.x + threadIdx.x) >> 5;
    int lane = threadIdx.x & 31;
    if (gw >= 2 * NB * NN) return;
    int row = gw & (NB * NN - 1);
    bool isA = gw < NB * NN;
    const float* src = isA ? fA : fB;
    const float* p = src + (size_t)row * NC;
    float x[4]; float ss = 0.f;
#pragma unroll
    for (int l = 0; l < 4; l++) { x[l] = p[lane + l * 32]; ss += x[l] * x[l]; }
    ss = warpSumF(ss);
    float sc = 1.f / fmaxf(sqrtf(ss), 1e-12f);
    __nv_bfloat16* q = (isA ? g_Ah : g_Bh) + (size_t)row * KS;
#pragma unroll
    for (int l = 0; l < 4; l++) {
        float v = x[l] * sc;
        __nv_bfloat16 h = __float2bfloat16(v);
        float r1 = v - __bfloat162float(h);
        __nv_bfloat16 m = __float2bfloat16(r1);
        float r2 = r1 - __bfloat162float(m);
        __nv_bfloat16 lo = __float2bfloat16(r2);
        int c = lane + l * 32;
        if (isA) {
            q[c]       = h;  q[c + 128] = m;  q[c + 256] = h;
            q[c + 384] = lo; q[c + 512] = h;  q[c + 640] = m;
        } else {
            q[c]       = h;  q[c + 128] = h;  q[c + 256] = m;
            q[c + 384] = h;  q[c + 512] = lo; q[c + 640] = m;
        }
    }
}

// -------- zero v --------
__global__ void zero_v_kernel() {
    int t = blockIdx.x * blockDim.x + threadIdx.x;
    if (t < NB * UVS) g_v[t] = 0.f;
}

// -------- bf16 tensor-core GEMM (K=768, sim store only) --------
__global__ void __launch_bounds__(256, 2) gemm_kernel(float* __restrict__ C) {
    __shared__ __align__(16) unsigned char sm[32 * 1024];
    const int b = blockIdx.z;
    const __nv_bfloat16* Ag = g_Ah + (size_t)b * NN * KS;
    const __nv_bfloat16* Bg = g_Bh + (size_t)b * NN * KS;
    float* Cb = C + (size_t)b * NN * NN;

    int tid = threadIdx.x, lane = tid & 31, wid = tid >> 5;
    int m_w = (wid & 1) * 64, n_w = (wid >> 1) * 32;
    int m0 = blockIdx.x * 128, n0 = blockIdx.y * 128;
    uint32_t smA = smem_u32(sm), smB = smA + 16384;

    float acc[4][4][4];
#pragma unroll
    for (int i = 0; i < 4; i++)
#pragma unroll
        for (int j = 0; j < 4; j++)
#pragma unroll
            for (int e = 0; e < 4; e++) acc[i][j][e] = 0.f;

    for (int kc = 0; kc < 12; kc++) {
#pragma unroll
        for (int q = tid; q < 2048; q += 256) {
            int isB = q >= 1024;
            int qq = q & 1023;
            int row = qq >> 3, c16 = qq & 7;
            const __nv_bfloat16* srcp = isB ? Bg : Ag;
            int grow = (isB ? n0 : m0) + row;
            uint4 w = *(const uint4*)&srcp[(size_t)grow * KS + kc * 64 + c16 * 8];
            int sw = (c16 * 16) ^ ((row & 7) * 16);
            *(uint4*)(sm + isB * 16384 + row * 128 + sw) = w;
        }
        __syncthreads();
#pragma unroll
        for (int ks = 0; ks < 4; ks++) {
            int kb = ks * 16;
            uint32_t a[4][4], bfr[4][2];
#pragma unroll
            for (int mi = 0; mi < 4; mi++) {
                int row = m_w + mi * 16 + (lane & 15);
                int col = kb + ((lane >> 4) << 3);
                uint32_t addr = smA + row * 128 + ((col * 2) ^ ((row & 7) * 16));
                ldsm_x4(a[mi][0], a[mi][1], a[mi][2], a[mi][3], addr);
            }
#pragma unroll
            for (int g = 0; g < 2; g++) {
                int row = n_w + g * 16 + ((lane >> 4) << 3) + (lane & 7);
                int col = kb + ((lane >> 3) & 1) * 8;
                uint32_t addr = smB + row * 128 + ((col * 2) ^ ((row & 7) * 16));
                uint32_t r0, r1, r2, r3;
                ldsm_x4(r0, r1, r2, r3, addr);
                bfr[2 * g][0] = r0; bfr[2 * g][1] = r1;
                bfr[2 * g + 1][0] = r2; bfr[2 * g + 1][1] = r3;
            }
#pragma unroll
            for (int mi = 0; mi < 4; mi++)
#pragma unroll
                for (int ni = 0; ni < 4; ni++)
                    mma16816(acc[mi][ni], a[mi], bfr[ni]);
        }
        __syncthreads();
    }

    int r0l = lane >> 2, c0l = (lane & 3) * 2;
#pragma unroll
    for (int mi = 0; mi < 4; mi++)
#pragma unroll
        for (int hf = 0; hf < 2; hf++) {
            int r = m_w + mi * 16 + r0l + hf * 8;
            size_t ro = (size_t)(m0 + r) * NN + n0 + n_w;
#pragma unroll
            for (int ni = 0; ni < 4; ni++) {
                float2 v = make_float2(acc[mi][ni][hf * 2], acc[mi][ni][hf * 2 + 1]);
                *(float2*)&Cb[ro + ni * 8 + c0l] = v;
            }
        }
}

// -------- fused Sinkhorn pass: u-update (16 rows/block) + column partials --------
// u[r] = NORMC - 20 - log( sum_j exp(20 s + v_old[j] - 20) + exp(v_old[N]-20) )
// pcol[blk][j] = sum_{r in blk} exp(20 s + v_old[j] + u_new[r])  (v_old divided
//                back out in finalize_v);  g_upart[blk] = sum_{r in blk} exp(u_new)
__global__ void __launch_bounds__(256) sink_uv_kernel(const float* __restrict__ sim) {
    __shared__ float sw[32];
    int blk = blockIdx.x, b = blockIdx.y, tid = threadIdx.x;
    int r0 = blk * 16;
    const float* vv = g_v + b * UVS;
    const float4* vv4 = (const float4*)vv;
    float vreg[16];
#pragma unroll
    for (int k = 0; k < 4; k++) {
        float4 t = vv4[tid + (k << 8)];
        vreg[4 * k] = t.x; vreg[4 * k + 1] = t.y;
        vreg[4 * k + 2] = t.z; vreg[4 * k + 3] = t.w;
    }
    float vN = vv[NN];
    float acc[16];
#pragma unroll
    for (int k = 0; k < 16; k++) acc[k] = 0.f;
    float usum = 0.f;

    for (int rr = 0; rr < 16; rr++) {
        int r = r0 + rr;
        const float4* s4 = (const float4*)(sim + (size_t)b * NN * NN + (size_t)r * NN);
        float e[16];
        float s = 0.f;
#pragma unroll
        for (int k = 0; k < 4; k++) {
            float4 sv = s4[tid + (k << 8)];
            e[4 * k]     = __expf(fmaf(20.f, sv.x, vreg[4 * k])     - 20.f);
            e[4 * k + 1] = __expf(fmaf(20.f, sv.y, vreg[4 * k + 1]) - 20.f);
            e[4 * k + 2] = __expf(fmaf(20.f, sv.z, vreg[4 * k + 2]) - 20.f);
            e[4 * k + 3] = __expf(fmaf(20.f, sv.w, vreg[4 * k + 3]) - 20.f);
            s += e[4 * k] + e[4 * k + 1] + e[4 * k + 2] + e[4 * k + 3];
        }
        if (tid == 0) s += __expf(vN - 20.f);
        float S = blockReduceSum(s, sw);
        float u_r = NORMC - 20.f - __logf(S);
        if (tid == 0) g_u[b * UVS + r] = u_r;
        usum += __expf(u_r);
        float sc = __expf(u_r + 20.f);
#pragma unroll
        for (int k = 0; k < 16; k++) acc[k] = fmaf(e[k], sc, acc[k]);
    }
    // store partials matching j layout: acc[4k+l] holds j = 4*(tid+256k)+l
    float4* pc4 = (float4*)(g_pcol + ((size_t)b * NBLK + blk) * NN);
#pragma unroll
    for (int k = 0; k < 4; k++)
        pc4[tid + (k << 8)] = make_float4(acc[4 * k], acc[4 * k + 1],
                                          acc[4 * k + 2], acc[4 * k + 3]);
    if (tid == 0) g_upart[b * NBLK + blk] = usum;
}

// -------- finalize v (deterministic, no atomics) --------
__global__ void __launch_bounds__(256) finalize_v_kernel(int it) {
    __shared__ float sw[32];
    int b = blockIdx.y, bx = blockIdx.x, tid = threadIdx.x;
    int j = bx * 256 + tid;
    // esum = sum_r exp(u_new[r])  (for dustbin column)
    float esum = blockReduceSum(g_upart[b * NBLK + tid], sw);
    // vsum_prev = sum_{j<=N} exp(v_old[j])  -> exp(uN) = 0.5 / vsum_prev
    float vp = (it > 0 && tid < NFB) ? g_vpart[(b * 2 + ((it - 1) & 1)) * NFB + tid] : 0.f;
    float vsum_prev = blockReduceSum(vp, sw);
    if (it == 0) vsum_prev = (float)(NN + 1);
    float expuN = 0.5f / vsum_prev;

    float v = 0.f;
    bool valid = (j <= NN);
    if (j < NN) {
        float v_old = g_v[b * UVS + j];
        const float* pc = g_pcol + (size_t)b * NBLK * NN + j;
        float s = 0.f;
#pragma unroll 8
        for (int blk = 0; blk < NBLK; blk++) s += pc[(size_t)blk * NN];
        // pcol carries exp(v_old[j]); divide back out
        v = NORMC - __logf(fmaf(s, __expf(-v_old), expuN));
    } else if (j == NN) {
        v = LOGMC - __logf(esum + expuN);
    }
    if (valid) g_v[b * UVS + j] = v;
    float ev = valid ? __expf(v) : 0.f;
    float bsum = blockReduceSum(ev, sw);
    if (tid == 0) g_vpart[(b * 2 + (it & 1)) * NFB + bx] = bsum;
}

// -------- per-row: entropy + top-8 --------
__global__ void __launch_bounds__(256) row_final_kernel(const float* __restrict__ sim,
                                                        const float* __restrict__ posB,
                                                        float* __restrict__ ent_out) {
    __shared__ float a[NN];
    __shared__ float sw[32];
    __shared__ int   swi[32];
    __shared__ float s_bv;
    __shared__ int   s_bi;
    int r = blockIdx.x, b = blockIdx.y, tid = threadIdx.x;
    const float4* vv4 = (const float4*)(g_v + b * UVS);
    const float4* s4 = (const float4*)(sim + (size_t)b * NN * NN + (size_t)r * NN);
    float ui = g_u[b * UVS + r];
    float4 tv[4];
#pragma unroll
    for (int k = 0; k < 4; k++) {
        int idx = tid + (k << 8);
        float4 s = s4[idx], v = vv4[idx];
        tv[k].x = fmaf(20.f, s.x, v.x); tv[k].y = fmaf(20.f, s.y, v.y);
        tv[k].z = fmaf(20.f, s.z, v.z); tv[k].w = fmaf(20.f, s.w, v.w);
        ((float4*)a)[idx] = tv[k];
    }
    float s = 0.f, e = 0.f;
#pragma unroll
    for (int k = 0; k < 4; k++) {
        s += __expf(tv[k].x + ui) + __expf(tv[k].y + ui)
           + __expf(tv[k].z + ui) + __expf(tv[k].w + ui);
    }
    float S = blockReduceSum(s, sw);
    float inv = 1.f / (S + 1e-8f);
#pragma unroll
    for (int k = 0; k < 4; k++) {
        float p;
        p = __expf(tv[k].x + ui) * inv; e -= p * __logf(p + 1e-8f);
        p = __expf(tv[k].y + ui) * inv; e -= p * __logf(p + 1e-8f);
        p = __expf(tv[k].z + ui) * inv; e -= p * __logf(p + 1e-8f);
        p = __expf(tv[k].w + ui) * inv; e -= p * __logf(p + 1e-8f);
    }
    float E = blockReduceSum(e, sw);
    if (tid == 0) ent_out[b * NN + r] = E;
    __syncthreads();
    long base = ((long)(b * NN + r)) * NK;
    int wid = tid >> 5, lane = tid & 31;
    for (int t = 0; t < NK; t++) {
        float bv = -FLT_MAX; int bi = 0;
#pragma unroll
        for (int k = 0; k < 16; k++) {
            int j = tid + (k << 8);
            float x = a[j];
            if (x > bv) { bv = x; bi = j; }
        }
#pragma unroll
        for (int o = 16; o; o >>= 1) {
            float ov = __shfl_xor_sync(0xffffffffu, bv, o);
            int   oi = __shfl_xor_sync(0xffffffffu, bi, o);
            if (ov > bv || (ov == bv && oi < bi)) { bv = ov; bi = oi; }
        }
        __syncthreads();
        if (lane == 0) { sw[wid] = bv; swi[wid] = bi; }
        __syncthreads();
        if (wid == 0) {
            float x = (lane < 8) ? sw[lane] : -FLT_MAX;
            int  xi = (lane < 8) ? swi[lane] : 0;
#pragma unroll
            for (int o = 4; o; o >>= 1) {
                float ov = __shfl_xor_sync(0xffffffffu, x, o);
                int   oi = __shfl_xor_sync(0xffffffffu, xi, o);
                if (ov > x || (ov == x && oi < xi)) { x = ov; xi = oi; }
            }
            if (lane == 0) { s_bv = x; s_bi = xi; }
        }
        __syncthreads();
        if (tid == 0) {
            int idx = s_bi;
            g_tkv[base + t] = expf(s_bv + ui);
            float px = posB[((size_t)b * NN + idx) * 2];
            float py = posB[((size_t)b * NN + idx) * 2 + 1];
            g_tkp[(base + t) * 2]     = px;
            g_tkp[(base + t) * 2 + 1] = py;
            a[idx] = -FLT_MAX;
        }
        __syncthreads();
    }
}

// -------- 7x7 local displacement variance (split over 4 z-slices) --------
__global__ void __launch_bounds__(256) geo_kernel(const float* __restrict__ posA) {
    __shared__ float dx[NN];
    __shared__ float dy[NN];
    int k = blockIdx.x, b = blockIdx.y, z = blockIdx.z, tid = threadIdx.x;
    for (int n = tid; n < NN; n += 256) {
        size_t tp = ((size_t)(b * NN + n) * NK + k) * 2;
        size_t pp = ((size_t)b * NN + n) * 2;
        dx[n] = g_tkp[tp]     - posA[pp];
        dy[n] = g_tkp[tp + 1] - posA[pp + 1];
    }
    __syncthreads();
    for (int n = z * 1024 + tid; n < (z + 1) * 1024; n += 256) {
        int h = n >> 6, w = n & 63;
        float s = 0.f; int cnt = 0;
        for (int di = -3; di <= 3; di++) {
            int hh = h + di;
            if ((unsigned)hh >= 64u) continue;
            for (int dj = -3; dj <= 3; dj++) {
                int ww = w + dj;
                if ((unsigned)ww >= 64u) continue;
                int m = hh * 64 + ww;
                s += dx[m] + dy[m];
                cnt += 2;
            }
        }
        float mean = s * (1.f / 98.f);
        float ssd = (float)(98 - cnt) * mean * mean;
        for (int di = -3; di <= 3; di++) {
            int hh = h + di;
            if ((unsigned)hh >= 64u) continue;
            for (int dj = -3; dj <= 3; dj++) {
                int ww = w + dj;
                if ((unsigned)ww >= 64u) continue;
                int m = hh * 64 + ww;
                float ax = dx[m] - mean, ay = dy[m] - mean;
                ssd += ax * ax + ay * ay;
            }
        }
        float var = ssd * (1.f / 97.f);
        g_geo[(size_t)(b * NN + n) * NK + k] = 1.f / (1.f + 100.f * var);
    }
}

// -------- softmax-combine -> refined warp --------
__global__ void combine_kernel(float* __restrict__ outRW) {
    int t = blockIdx.x * blockDim.x + threadIdx.x;
    if (t >= NB * NN) return;
    size_t base = (size_t)t * NK;
    float c[NK]; float m = -FLT_MAX;
#pragma unroll
    for (int k = 0; k < NK; k++) {
        c[k] = g_tkv[base + k] + 1.5f * g_geo[base + k];
        m = fmaxf(m, c[k]);
    }
    float sw = 0.f, rx = 0.f, ry = 0.f;
#pragma unroll
    for (int k = 0; k < NK; k++) {
        float w = expf((c[k] - m) * 20.f);
        sw += w;
        rx += g_tkp[(base + k) * 2]     * w;
        ry += g_tkp[(base + k) * 2 + 1] * w;
    }
    outRW[(size_t)t * 2]     = rx / sw;
    outRW[(size_t)t * 2 + 1] = ry / sw;
}

extern "C" void kernel_launch(void* const* d_in, const int* in_sizes, int n_in,
                              void* d_out, int out_size) {
    const float* fA = (const float*)d_in[0];
    const float* fB = (const float*)d_in[1];
    const float* pA = (const float*)d_in[2];
    const float* pB = (const float*)d_in[3];
    (void)in_sizes; (void)n_in; (void)out_size;

    float* out = (float*)d_out;
    float* out_rw  = out;                          // [2,4096,2]
    float* out_ent = out + NB * NN * 2;            // [2,4096]
    float* out_sim = out + NB * NN * 2 + NB * NN;  // [2,4096,4096]

    normalize_kernel<<<(2 * NB * NN * 32 + 255) / 256, 256>>>(fA, fB);
    zero_v_kernel<<<(NB * UVS + 255) / 256, 256>>>();
    gemm_kernel<<<dim3(32, 32, NB), 256>>>(out_sim);
    for (int it = 0; it < 5; it++) {
        sink_uv_kernel<<<dim3(NBLK, NB), 256>>>(out_sim);
        finalize_v_kernel<<<dim3(NFB, NB), 256>>>(it);
    }
    row_final_kernel<<<dim3(NN, NB), 256>>>(out_sim, pB, out_ent);
    geo_kernel<<<dim3(NK, NB, 4), 256>>>(pA);
    combine_kernel<<<(NB * NN + 255) / 256, 256>>>(out_rw);
}

// round 14
// speedup vs baseline: 1.3064x; 1.0510x over previous
#include <cuda_runtime.h>
#include <cuda_bf16.h>
#include <cstdint>
#include <math.h>
#include <float.h>

#define NB 2
#define NN 4096
#define NC 128
#define NK 8
#define UVS 4100   // padded stride for u/v so each batch slice is 16B-aligned
#define KS 768     // 6-term split: A=[h|m|h|l|h|m], B=[h|h|m|h|l|m]
#define NBLK 256   // row-blocks per batch in fused sinkhorn pass (16 rows each)
#define NFB 17     // finalize blocks per batch (17*256 >= 4097)

#define NORMC  (-9.010913347279289f)   // -log(8192)
#define LOGMC  (-0.6931471805599453f)  // log(4096) - log(8192)

// -------- scratch (static device globals; no allocation) --------
__device__ __nv_bfloat16 g_Ah[(size_t)NB * NN * KS];
__device__ __nv_bfloat16 g_Bh[(size_t)NB * NN * KS];
__device__ float g_u[NB * UVS];
__device__ float g_v[NB * UVS];
__device__ float g_pcol[(size_t)NB * NBLK * NN];  // column partials (8.4MB)
__device__ float g_upart[NB * NBLK];              // per-block sum exp(u_new)
__device__ float g_vpart[NB * 2 * NFB];           // ping-pong per-block sum exp(v_new)
__device__ float g_tkv[NB * NN * NK];
__device__ float g_tkp[NB * NN * NK * 2];
__device__ float g_geo[NB * NN * NK];

// -------- reduction helpers --------
__device__ __forceinline__ float warpSumF(float v) {
#pragma unroll
    for (int o = 16; o; o >>= 1) v += __shfl_xor_sync(0xffffffffu, v, o);
    return v;
}
__device__ __forceinline__ float blockReduceSum(float v, float* sw) {
    v = warpSumF(v);
    int wid = threadIdx.x >> 5, lane = threadIdx.x & 31;
    __syncthreads();
    if (lane == 0) sw[wid] = v;
    __syncthreads();
    if (wid == 0) {
        float x = (lane < 8) ? sw[lane] : 0.f;
        x = warpSumF(x);
        if (lane == 0) sw[0] = x;
    }
    __syncthreads();
    return sw[0];
}

// -------- mma / cp.async helpers --------
__device__ __forceinline__ uint32_t smem_u32(const void* p) {
    return (uint32_t)__cvta_generic_to_shared(p);
}
__device__ __forceinline__ void cp16(uint32_t dst, const void* src) {
    asm volatile("cp.async.cg.shared.global [%0], [%1], 16;" :: "r"(dst), "l"(src));
}
__device__ __forceinline__ void ldsm_x4(uint32_t& r0, uint32_t& r1, uint32_t& r2,
                                        uint32_t& r3, uint32_t addr) {
    asm volatile("ldmatrix.sync.aligned.m8n8.x4.shared.b16 {%0,%1,%2,%3}, [%4];"
                 : "=r"(r0), "=r"(r1), "=r"(r2), "=r"(r3) : "r"(addr));
}
__device__ __forceinline__ void mma16816(float* d, const uint32_t* a, const uint32_t* b) {
    asm volatile(
        "mma.sync.aligned.m16n8k16.row.col.f32.bf16.bf16.f32 "
        "{%0,%1,%2,%3}, {%4,%5,%6,%7}, {%8,%9}, {%0,%1,%2,%3};"
        : "+f"(d[0]), "+f"(d[1]), "+f"(d[2]), "+f"(d[3])
        : "r"(a[0]), "r"(a[1]), "r"(a[2]), "r"(a[3]), "r"(b[0]), "r"(b[1]));
}

// -------- row L2 normalize + bf16 3-limb split --------
__global__ void __launch_bounds__(256) normalize_kernel(const float* __restrict__ fA,
                                                        const float* __restrict__ fB) {
    int gw = (blockIdx.x * blockDim.x + threadIdx.x) >> 5;
    int lane = threadIdx.x & 31;
    if (gw >= 2 * NB * NN) return;
    int row = gw & (NB * NN - 1);
    bool isA = gw < NB * NN;
    const float* src = isA ? fA : fB;
    const float* p = src + (size_t)row * NC;
    float x[4]; float ss = 0.f;
#pragma unroll
    for (int l = 0; l < 4; l++) { x[l] = p[lane + l * 32]; ss += x[l] * x[l]; }
    ss = warpSumF(ss);
    float sc = 1.f / fmaxf(sqrtf(ss), 1e-12f);
    __nv_bfloat16* q = (isA ? g_Ah : g_Bh) + (size_t)row * KS;
#pragma unroll
    for (int l = 0; l < 4; l++) {
        float v = x[l] * sc;
        __nv_bfloat16 h = __float2bfloat16(v);
        float r1 = v - __bfloat162float(h);
        __nv_bfloat16 m = __float2bfloat16(r1);
        float r2 = r1 - __bfloat162float(m);
        __nv_bfloat16 lo = __float2bfloat16(r2);
        int c = lane + l * 32;
        if (isA) {
            q[c]       = h;  q[c + 128] = m;  q[c + 256] = h;
            q[c + 384] = lo; q[c + 512] = h;  q[c + 640] = m;
        } else {
            q[c]       = h;  q[c + 128] = h;  q[c + 256] = m;
            q[c + 384] = h;  q[c + 512] = lo; q[c + 640] = m;
        }
    }
}

// -------- zero v --------
__global__ void zero_v_kernel() {
    int t = blockIdx.x * blockDim.x + threadIdx.x;
    if (t < NB * UVS) g_v[t] = 0.f;
}

// -------- GEMM chunk loader (cp.async, 128x64 bf16 A and B, swizzled) --------
__device__ __forceinline__ void gemm_load_chunk(uint32_t smBase, int stage,
                                                const __nv_bfloat16* Ag,
                                                const __nv_bfloat16* Bg,
                                                int m0, int n0, int kc, int tid) {
#pragma unroll
    for (int q = tid; q < 2048; q += 256) {
        int isB = q >= 1024;
        int qq = q & 1023;
        int row = qq >> 3, c16 = qq & 7;
        const __nv_bfloat16* srcp = isB ? Bg : Ag;
        int grow = (isB ? n0 : m0) + row;
        const void* src = &srcp[(size_t)grow * KS + kc * 64 + c16 * 8];
        int sw = (c16 * 16) ^ ((row & 7) * 16);
        cp16(smBase + stage * 32768 + isB * 16384 + row * 128 + sw, src);
    }
    asm volatile("cp.async.commit_group;" ::: "memory");
}

// -------- bf16 tensor-core GEMM (K=768, double-buffered cp.async, 2 CTA/SM) ----
__global__ void __launch_bounds__(256, 2) gemm_kernel(float* __restrict__ C) {
    extern __shared__ __align__(16) unsigned char smx[];   // 64KB: 2 stages
    const int b = blockIdx.z;
    const __nv_bfloat16* Ag = g_Ah + (size_t)b * NN * KS;
    const __nv_bfloat16* Bg = g_Bh + (size_t)b * NN * KS;
    float* Cb = C + (size_t)b * NN * NN;

    int tid = threadIdx.x, lane = tid & 31, wid = tid >> 5;
    int m_w = (wid & 1) * 64, n_w = (wid >> 1) * 32;
    int m0 = blockIdx.x * 128, n0 = blockIdx.y * 128;
    uint32_t smBase = smem_u32(smx);

    float acc[4][4][4];
#pragma unroll
    for (int i = 0; i < 4; i++)
#pragma unroll
        for (int j = 0; j < 4; j++)
#pragma unroll
            for (int e = 0; e < 4; e++) acc[i][j][e] = 0.f;

    gemm_load_chunk(smBase, 0, Ag, Bg, m0, n0, 0, tid);

    for (int kc = 0; kc < 12; kc++) {
        if (kc < 11) {
            gemm_load_chunk(smBase, (kc + 1) & 1, Ag, Bg, m0, n0, kc + 1, tid);
            asm volatile("cp.async.wait_group 1;" ::: "memory");
        } else {
            asm volatile("cp.async.wait_group 0;" ::: "memory");
        }
        __syncthreads();
        uint32_t smA = smBase + (kc & 1) * 32768;
        uint32_t smB = smA + 16384;
#pragma unroll
        for (int ks = 0; ks < 4; ks++) {
            int kb = ks * 16;
            uint32_t a[4][4], bfr[4][2];
#pragma unroll
            for (int mi = 0; mi < 4; mi++) {
                int row = m_w + mi * 16 + (lane & 15);
                int col = kb + ((lane >> 4) << 3);
                uint32_t addr = smA + row * 128 + ((col * 2) ^ ((row & 7) * 16));
                ldsm_x4(a[mi][0], a[mi][1], a[mi][2], a[mi][3], addr);
            }
#pragma unroll
            for (int g = 0; g < 2; g++) {
                int row = n_w + g * 16 + ((lane >> 4) << 3) + (lane & 7);
                int col = kb + ((lane >> 3) & 1) * 8;
                uint32_t addr = smB + row * 128 + ((col * 2) ^ ((row & 7) * 16));
                uint32_t r0, r1, r2, r3;
                ldsm_x4(r0, r1, r2, r3, addr);
                bfr[2 * g][0] = r0; bfr[2 * g][1] = r1;
                bfr[2 * g + 1][0] = r2; bfr[2 * g + 1][1] = r3;
            }
#pragma unroll
            for (int mi = 0; mi < 4; mi++)
#pragma unroll
                for (int ni = 0; ni < 4; ni++)
                    mma16816(acc[mi][ni], a[mi], bfr[ni]);
        }
        __syncthreads();
    }

    int r0l = lane >> 2, c0l = (lane & 3) * 2;
#pragma unroll
    for (int mi = 0; mi < 4; mi++)
#pragma unroll
        for (int hf = 0; hf < 2; hf++) {
            int r = m_w + mi * 16 + r0l + hf * 8;
            size_t ro = (size_t)(m0 + r) * NN + n0 + n_w;
#pragma unroll
            for (int ni = 0; ni < 4; ni++) {
                float2 v = make_float2(acc[mi][ni][hf * 2], acc[mi][ni][hf * 2 + 1]);
                *(float2*)&Cb[ro + ni * 8 + c0l] = v;
            }
        }
}

// -------- fused Sinkhorn pass: u-update (16 rows/block) + column partials --------
__global__ void __launch_bounds__(256) sink_uv_kernel(const float* __restrict__ sim) {
    __shared__ float sw[32];
    int blk = blockIdx.x, b = blockIdx.y, tid = threadIdx.x;
    int r0 = blk * 16;
    const float* vv = g_v + b * UVS;
    const float4* vv4 = (const float4*)vv;
    float vreg[16];
#pragma unroll
    for (int k = 0; k < 4; k++) {
        float4 t = vv4[tid + (k << 8)];
        vreg[4 * k] = t.x; vreg[4 * k + 1] = t.y;
        vreg[4 * k + 2] = t.z; vreg[4 * k + 3] = t.w;
    }
    float vN = vv[NN];
    float acc[16];
#pragma unroll
    for (int k = 0; k < 16; k++) acc[k] = 0.f;
    float usum = 0.f;

    for (int rr = 0; rr < 16; rr++) {
        int r = r0 + rr;
        const float4* s4 = (const float4*)(sim + (size_t)b * NN * NN + (size_t)r * NN);
        float e[16];
        float s = 0.f;
#pragma unroll
        for (int k = 0; k < 4; k++) {
            float4 sv = s4[tid + (k << 8)];
            e[4 * k]     = __expf(fmaf(20.f, sv.x, vreg[4 * k])     - 20.f);
            e[4 * k + 1] = __expf(fmaf(20.f, sv.y, vreg[4 * k + 1]) - 20.f);
            e[4 * k + 2] = __expf(fmaf(20.f, sv.z, vreg[4 * k + 2]) - 20.f);
            e[4 * k + 3] = __expf(fmaf(20.f, sv.w, vreg[4 * k + 3]) - 20.f);
            s += e[4 * k] + e[4 * k + 1] + e[4 * k + 2] + e[4 * k + 3];
        }
        if (tid == 0) s += __expf(vN - 20.f);
        float S = blockReduceSum(s, sw);
        float u_r = NORMC - 20.f - __logf(S);
        if (tid == 0) g_u[b * UVS + r] = u_r;
        usum += __expf(u_r);
        float sc = __expf(u_r + 20.f);
#pragma unroll
        for (int k = 0; k < 16; k++) acc[k] = fmaf(e[k], sc, acc[k]);
    }
    float4* pc4 = (float4*)(g_pcol + ((size_t)b * NBLK + blk) * NN);
#pragma unroll
    for (int k = 0; k < 4; k++)
        pc4[tid + (k << 8)] = make_float4(acc[4 * k], acc[4 * k + 1],
                                          acc[4 * k + 2], acc[4 * k + 3]);
    if (tid == 0) g_upart[b * NBLK + blk] = usum;
}

// -------- finalize v (deterministic, no atomics) --------
__global__ void __launch_bounds__(256) finalize_v_kernel(int it) {
    __shared__ float sw[32];
    int b = blockIdx.y, bx = blockIdx.x, tid = threadIdx.x;
    int j = bx * 256 + tid;
    float esum = blockReduceSum(g_upart[b * NBLK + tid], sw);
    float vp = (it > 0 && tid < NFB) ? g_vpart[(b * 2 + ((it - 1) & 1)) * NFB + tid] : 0.f;
    float vsum_prev = blockReduceSum(vp, sw);
    if (it == 0) vsum_prev = (float)(NN + 1);
    float expuN = 0.5f / vsum_prev;

    float v = 0.f;
    bool valid = (j <= NN);
    if (j < NN) {
        float v_old = g_v[b * UVS + j];
        const float* pc = g_pcol + (size_t)b * NBLK * NN + j;
        float s = 0.f;
#pragma unroll 8
        for (int blk = 0; blk < NBLK; blk++) s += pc[(size_t)blk * NN];
        v = NORMC - __logf(fmaf(s, __expf(-v_old), expuN));
    } else if (j == NN) {
        v = LOGMC - __logf(esum + expuN);
    }
    if (valid) g_v[b * UVS + j] = v;
    float ev = valid ? __expf(v) : 0.f;
    float bsum = blockReduceSum(ev, sw);
    if (tid == 0) g_vpart[(b * 2 + (it & 1)) * NFB + bx] = bsum;
}

// -------- per-row: entropy + top-8 --------
__global__ void __launch_bounds__(256) row_final_kernel(const float* __restrict__ sim,
                                                        const float* __restrict__ posB,
                                                        float* __restrict__ ent_out) {
    __shared__ float a[NN];
    __shared__ float sw[32];
    __shared__ int   swi[32];
    __shared__ float s_bv;
    __shared__ int   s_bi;
    int r = blockIdx.x, b = blockIdx.y, tid = threadIdx.x;
    const float4* vv4 = (const float4*)(g_v + b * UVS);
    const float4* s4 = (const float4*)(sim + (size_t)b * NN * NN + (size_t)r * NN);
    float ui = g_u[b * UVS + r];
    float4 tv[4];
#pragma unroll
    for (int k = 0; k < 4; k++) {
        int idx = tid + (k << 8);
        float4 s = s4[idx], v = vv4[idx];
        tv[k].x = fmaf(20.f, s.x, v.x); tv[k].y = fmaf(20.f, s.y, v.y);
        tv[k].z = fmaf(20.f, s.z, v.z); tv[k].w = fmaf(20.f, s.w, v.w);
        ((float4*)a)[idx] = tv[k];
    }
    float s = 0.f, e = 0.f;
#pragma unroll
    for (int k = 0; k < 4; k++) {
        s += __expf(tv[k].x + ui) + __expf(tv[k].y + ui)
           + __expf(tv[k].z + ui) + __expf(tv[k].w + ui);
    }
    float S = blockReduceSum(s, sw);
    float inv = 1.f / (S + 1e-8f);
#pragma unroll
    for (int k = 0; k < 4; k++) {
        float p;
        p = __expf(tv[k].x + ui) * inv; e -= p * __logf(p + 1e-8f);
        p = __expf(tv[k].y + ui) * inv; e -= p * __logf(p + 1e-8f);
        p = __expf(tv[k].z + ui) * inv; e -= p * __logf(p + 1e-8f);
        p = __expf(tv[k].w + ui) * inv; e -= p * __logf(p + 1e-8f);
    }
    float E = blockReduceSum(e, sw);
    if (tid == 0) ent_out[b * NN + r] = E;
    __syncthreads();
    long base = ((long)(b * NN + r)) * NK;
    int wid = tid >> 5, lane = tid & 31;
    for (int t = 0; t < NK; t++) {
        float bv = -FLT_MAX; int bi = 0;
#pragma unroll
        for (int k = 0; k < 16; k++) {
            int j = tid + (k << 8);
            float x = a[j];
            if (x > bv) { bv = x; bi = j; }
        }
#pragma unroll
        for (int o = 16; o; o >>= 1) {
            float ov = __shfl_xor_sync(0xffffffffu, bv, o);
            int   oi = __shfl_xor_sync(0xffffffffu, bi, o);
            if (ov > bv || (ov == bv && oi < bi)) { bv = ov; bi = oi; }
        }
        __syncthreads();
        if (lane == 0) { sw[wid] = bv; swi[wid] = bi; }
        __syncthreads();
        if (wid == 0) {
            float x = (lane < 8) ? sw[lane] : -FLT_MAX;
            int  xi = (lane < 8) ? swi[lane] : 0;
#pragma unroll
            for (int o = 4; o; o >>= 1) {
                float ov = __shfl_xor_sync(0xffffffffu, x, o);
                int   oi = __shfl_xor_sync(0xffffffffu, xi, o);
                if (ov > x || (ov == x && oi < xi)) { x = ov; xi = oi; }
            }
            if (lane == 0) { s_bv = x; s_bi = xi; }
        }
        __syncthreads();
        if (tid == 0) {
            int idx = s_bi;
            g_tkv[base + t] = expf(s_bv + ui);
            float px = posB[((size_t)b * NN + idx) * 2];
            float py = posB[((size_t)b * NN + idx) * 2 + 1];
            g_tkp[(base + t) * 2]     = px;
            g_tkp[(base + t) * 2 + 1] = py;
            a[idx] = -FLT_MAX;
        }
        __syncthreads();
    }
}

// -------- 7x7 local displacement variance (split over 4 z-slices) --------
__global__ void __launch_bounds__(256) geo_kernel(const float* __restrict__ posA) {
    __shared__ float dx[NN];
    __shared__ float dy[NN];
    int k = blockIdx.x, b = blockIdx.y, z = blockIdx.z, tid = threadIdx.x;
    for (int n = tid; n < NN; n += 256) {
        size_t tp = ((size_t)(b * NN + n) * NK + k) * 2;
        size_t pp = ((size_t)b * NN + n) * 2;
        dx[n] = g_tkp[tp]     - posA[pp];
        dy[n] = g_tkp[tp + 1] - posA[pp + 1];
    }
    __syncthreads();
    for (int n = z * 1024 + tid; n < (z + 1) * 1024; n += 256) {
        int h = n >> 6, w = n & 63;
        float s = 0.f; int cnt = 0;
        for (int di = -3; di <= 3; di++) {
            int hh = h + di;
            if ((unsigned)hh >= 64u) continue;
            for (int dj = -3; dj <= 3; dj++) {
                int ww = w + dj;
                if ((unsigned)ww >= 64u) continue;
                int m = hh * 64 + ww;
                s += dx[m] + dy[m];
                cnt += 2;
            }
        }
        float mean = s * (1.f / 98.f);
        float ssd = (float)(98 - cnt) * mean * mean;
        for (int di = -3; di <= 3; di++) {
            int hh = h + di;
            if ((unsigned)hh >= 64u) continue;
            for (int dj = -3; dj <= 3; dj++) {
                int ww = w + dj;
                if ((unsigned)ww >= 64u) continue;
                int m = hh * 64 + ww;
                float ax = dx[m] - mean, ay = dy[m] - mean;
                ssd += ax * ax + ay * ay;
            }
        }
        float var = ssd * (1.f / 97.f);
        g_geo[(size_t)(b * NN + n) * NK + k] = 1.f / (1.f + 100.f * var);
    }
}

// -------- softmax-combine -> refined warp --------
__global__ void combine_kernel(float* __restrict__ outRW) {
    int t = blockIdx.x * blockDim.x + threadIdx.x;
    if (t >= NB * NN) return;
    size_t base = (size_t)t * NK;
    float c[NK]; float m = -FLT_MAX;
#pragma unroll
    for (int k = 0; k < NK; k++) {
        c[k] = g_tkv[base + k] + 1.5f * g_geo[base + k];
        m = fmaxf(m, c[k]);
    }
    float sw = 0.f, rx = 0.f, ry = 0.f;
#pragma unroll
    for (int k = 0; k < NK; k++) {
        float w = expf((c[k] - m) * 20.f);
        sw += w;
        rx += g_tkp[(base + k) * 2]     * w;
        ry += g_tkp[(base + k) * 2 + 1] * w;
    }
    outRW[(size_t)t * 2]     = rx / sw;
    outRW[(size_t)t * 2 + 1] = ry / sw;
}

extern "C" void kernel_launch(void* const* d_in, const int* in_sizes, int n_in,
                              void* d_out, int out_size) {
    const float* fA = (const float*)d_in[0];
    const float* fB = (const float*)d_in[1];
    const float* pA = (const float*)d_in[2];
    const float* pB = (const float*)d_in[3];
    (void)in_sizes; (void)n_in; (void)out_size;

    float* out = (float*)d_out;
    float* out_rw  = out;                          // [2,4096,2]
    float* out_ent = out + NB * NN * 2;            // [2,4096]
    float* out_sim = out + NB * NN * 2 + NB * NN;  // [2,4096,4096]

    cudaFuncSetAttribute(gemm_kernel, cudaFuncAttributeMaxDynamicSharedMemorySize,
                         65536);

    normalize_kernel<<<(2 * NB * NN * 32 + 255) / 256, 256>>>(fA, fB);
    zero_v_kernel<<<(NB * UVS + 255) / 256, 256>>>();
    gemm_kernel<<<dim3(32, 32, NB), 256, 65536>>>(out_sim);
    for (int it = 0; it < 5; it++) {
        sink_uv_kernel<<<dim3(NBLK, NB), 256>>>(out_sim);
        finalize_v_kernel<<<dim3(NFB, NB), 256>>>(it);
    }
    row_final_kernel<<<dim3(NN, NB), 256>>>(out_sim, pB, out_ent);
    geo_kernel<<<dim3(NK, NB, 4), 256>>>(pA);
    combine_kernel<<<(NB * NN + 255) / 256, 256>>>(out_rw);
}